// round 14
// baseline (speedup 1.0000x reference)
#include <cuda_runtime.h>
#include <math.h>
#include <stdint.h>

#define H_DIM 2048
#define NH 16
#define DN 128
#define DR 64
#define DQ 192
#define DV 128
#define KVR 512
#define QR 1536
#define SEQ 2048
#define THETA 100000.0f
#define RMS_EPS 1e-5f

// ---------------- scratch ----------------
__device__ float g_qlat[SEQ * QR];
__device__ float g_q[SEQ * NH * DQ];
__device__ float g_kvlat[SEQ * KVR];
__device__ float g_k[SEQ * NH * DQ];
__device__ float g_v[SEQ * NH * DV];
__device__ float g_attn[SEQ * NH * DV];
// pre-rounded tf32 copies; weights stored TRANSPOSED (n-major: Wt[n][k])
__device__ float g_xr[SEQ * H_DIM];
__device__ float g_wqd[QR * H_DIM];
__device__ float g_wqu[NH * DQ * QR];
__device__ float g_wkvd[KVR * H_DIM];
__device__ float g_wku[NH * DQ * KVR];
__device__ float g_wvu[NH * DV * KVR];
__device__ float g_wo[H_DIM * NH * DV];

// ---------------- helpers ----------------
__device__ __forceinline__ uint32_t f2tf32(float v) {
    uint32_t u;
    asm("cvt.rna.tf32.f32 %0, %1;" : "=r"(u) : "f"(v));
    return u;
}

__device__ __forceinline__ void mma_tf32(
    float& c0, float& c1, float& c2, float& c3,
    uint32_t a0, uint32_t a1, uint32_t a2, uint32_t a3,
    uint32_t b0, uint32_t b1)
{
    asm volatile(
        "mma.sync.aligned.m16n8k8.row.col.f32.tf32.tf32.f32 "
        "{%0,%1,%2,%3}, {%4,%5,%6,%7}, {%8,%9}, {%0,%1,%2,%3};"
        : "+f"(c0), "+f"(c1), "+f"(c2), "+f"(c3)
        : "r"(a0), "r"(a1), "r"(a2), "r"(a3), "r"(b0), "r"(b1));
}

__device__ __forceinline__ void ldsm4(uint32_t& r0, uint32_t& r1, uint32_t& r2, uint32_t& r3,
                                      uint32_t saddr)
{
    asm volatile("ldmatrix.sync.aligned.m8n8.x4.shared.b16 {%0,%1,%2,%3}, [%4];"
                 : "=r"(r0), "=r"(r1), "=r"(r2), "=r"(r3) : "r"(saddr));
}

__device__ __forceinline__ void cpa16(uint32_t saddr, const void* g) {
    asm volatile("cp.async.cg.shared.global [%0], [%1], 16;" :: "r"(saddr), "l"(g));
}
#define CP_COMMIT() asm volatile("cp.async.commit_group;")
#define CP_WAITG1() asm volatile("cp.async.wait_group 1;")
#define CP_WAIT1()  asm volatile("cp.async.wait_group 1;")

// fast exp on FMA pipe
__device__ __forceinline__ float fexp(float x) {
    x = fmaxf(x, -80.f) * 1.4426950408889634f;
    float z = x + 12582912.f;
    int n = __float_as_int(z) - 0x4B400000;
    float f = x - (z - 12582912.f);
    float p = 1.3333558146e-3f;
    p = fmaf(p, f, 9.6180209e-3f);
    p = fmaf(p, f, 5.5504109e-2f);
    p = fmaf(p, f, 2.4022651e-1f);
    p = fmaf(p, f, 6.9314718e-1f);
    p = fmaf(p, f, 1.0f);
    return p * __int_as_float((n + 127) << 23);
}

// ---------------- prepass: round x; transpose+round weights ----------------
__global__ __launch_bounds__(256) void round_x_kernel(const float* __restrict__ x)
{
    int i = blockIdx.x * 256 + threadIdx.x;
    if (i >= SEQ * H_DIM / 4) return;
    float4 t = reinterpret_cast<const float4*>(x)[i];
    uint4 u = make_uint4(f2tf32(t.x), f2tf32(t.y), f2tf32(t.z), f2tf32(t.w));
    reinterpret_cast<uint4*>(g_xr)[i] = u;
}

// src[K][N] -> dst[N][K], tf32-rounded. grid (N/32, K/32), 256 thr (32x8)
__global__ __launch_bounds__(256) void transpose_round_kernel(
    const float* __restrict__ src, float* __restrict__ dst, int K, int N)
{
    __shared__ float t[32][33];
    const int n0 = blockIdx.x * 32, k0 = blockIdx.y * 32;
    const int tx = threadIdx.x & 31, ty = threadIdx.x >> 5;
#pragma unroll
    for (int i = 0; i < 32; i += 8)
        t[ty + i][tx] = src[(size_t)(k0 + ty + i) * N + n0 + tx];
    __syncthreads();
    uint32_t* du = reinterpret_cast<uint32_t*>(dst);
#pragma unroll
    for (int i = 0; i < 32; i += 8)
        du[(size_t)(n0 + ty + i) * K + k0 + tx] = f2tf32(t[tx][ty + i]);
}

// ---------------- tf32 GEMM v8: both operands n/m-major, all-ldmatrix frags ----------
// A[M][K] row-major; Bt[N][K] row-major (transposed weights). 5-stage cp.async,
// one barrier per 2 K-iters (R12 scheme). Bit-identical MMA order to v5/v7.
#define ST 20
#define TSZ (128 * ST)
#define STG 5
#define GEMM_SMEM (STG * 2 * TSZ * 4)

extern __shared__ float dsm[];

__global__ __launch_bounds__(256) void sgemm_v8(
    const float* __restrict__ A1, const float* __restrict__ Bt1, float* __restrict__ C1,
    int nb1, int N1, int K1,
    const float* __restrict__ A2, const float* __restrict__ Bt2, float* __restrict__ C2,
    int nb2, int N2, int K2,
    const float* __restrict__ A3, const float* __restrict__ Bt3, float* __restrict__ C3,
    int N3, int K3,
    int roundC)
{
    float* Asf = dsm;
    float* Bsf = dsm + STG * TSZ;
    const uint32_t sbA = (uint32_t)__cvta_generic_to_shared(Asf);
    const uint32_t sbB = (uint32_t)__cvta_generic_to_shared(Bsf);

    int bx = blockIdx.x;
    const int by = blockIdx.y;
    const float* A;
    const float* Bt;
    float* C;
    int N, K;
    if (bx < nb1)            { A = A1; Bt = Bt1; C = C1; N = N1; K = K1; }
    else if (bx < nb1 + nb2) { A = A2; Bt = Bt2; C = C2; N = N2; K = K2; bx -= nb1; }
    else                     { A = A3; Bt = Bt3; C = C3; N = N3; K = K3; bx -= nb1 + nb2; }

    const int tid = threadIdx.x;
    const int wid = tid >> 5, lane = tid & 31;
    const int g = lane >> 2, tig = lane & 3;
    const int wm = wid & 1, wn = wid >> 1;

    // loads: same pattern for A and Bt (row r, 16B chunk)
    const int am = tid >> 2, ak4 = (tid & 3) * 4;
    const float* pA0 = A + (size_t)(by * 128 + am) * K + ak4;
    const float* pA1 = pA0 + (size_t)64 * K;
    const float* pB0 = Bt + (size_t)(bx * 128 + am) * K + ak4;
    const float* pB1 = pB0 + (size_t)64 * K;

    const uint32_t saA0 = sbA + (am * ST + ak4) * 4;
    const uint32_t saA1 = sbA + ((am + 64) * ST + ak4) * 4;
    const uint32_t saB0 = sbB + (am * ST + ak4) * 4;
    const uint32_t saB1 = sbB + ((am + 64) * ST + ak4) * 4;

    const uint32_t lmA = sbA + (((wm * 64 + (lane & 15)) * ST + (lane >> 4) * 4) * 4);
    const uint32_t lmB = sbB + (((wn * 32 + (lane & 15)) * ST + (lane >> 4) * 4) * 4);

    float acc[4][4][4];
#pragma unroll
    for (int i = 0; i < 4; i++)
#pragma unroll
        for (int j = 0; j < 4; j++)
#pragma unroll
            for (int r = 0; r < 4; r++) acc[i][j][r] = 0.f;

    const int nt = K >> 4;

#define GEMM_ISSUE(T) do {                                                    \
        if ((T) < nt) {                                                       \
            int _s = (T) % STG;                                               \
            int _k0 = (T) * 16;                                               \
            cpa16(saA0 + _s * TSZ * 4, pA0 + _k0);                            \
            cpa16(saA1 + _s * TSZ * 4, pA1 + _k0);                            \
            cpa16(saB0 + _s * TSZ * 4, pB0 + _k0);                            \
            cpa16(saB1 + _s * TSZ * 4, pB1 + _k0);                            \
        }                                                                     \
        CP_COMMIT();                                                          \
    } while (0)

#define GEMM_COMPUTE(SLOT) do {                                               \
        const uint32_t _lA = lmA + (SLOT) * TSZ * 4;                          \
        const uint32_t _lB = lmB + (SLOT) * TSZ * 4;                          \
        _Pragma("unroll")                                                     \
        for (int kk = 0; kk < 16; kk += 8) {                                  \
            uint32_t a[4][4], b[4][2];                                        \
            _Pragma("unroll")                                                 \
            for (int i = 0; i < 4; i++)                                       \
                ldsm4(a[i][0], a[i][1], a[i][2], a[i][3],                     \
                      _lA + (kk + i * 16 * ST) * 4);                          \
            ldsm4(b[0][0], b[1][0], b[0][1], b[1][1], _lB + kk * 4);          \
            ldsm4(b[2][0], b[3][0], b[2][1], b[3][1],                         \
                  _lB + (kk + 16 * ST) * 4);                                  \
            _Pragma("unroll")                                                 \
            for (int i = 0; i < 4; i++)                                       \
                _Pragma("unroll")                                             \
                for (int j = 0; j < 4; j++)                                   \
                    mma_tf32(acc[i][j][0], acc[i][j][1], acc[i][j][2],        \
                             acc[i][j][3], a[i][0], a[i][1], a[i][2],         \
                             a[i][3], b[j][0], b[j][1]);                      \
        }                                                                     \
    } while (0)

    GEMM_ISSUE(0);
    GEMM_ISSUE(1);
    GEMM_ISSUE(2);

    for (int it = 0; it < nt; it += 2) {
        CP_WAITG1();
        __syncthreads();

        GEMM_ISSUE(it + 3);
        GEMM_COMPUTE(it % STG);
        GEMM_ISSUE(it + 4);
        GEMM_COMPUTE((it + 1) % STG);
    }
#undef GEMM_ISSUE
#undef GEMM_COMPUTE

    float* Cb = C + (size_t)(by * 128) * N + bx * 128;
    if (roundC) {
#pragma unroll
        for (int i = 0; i < 4; i++) {
            int r0 = wm * 64 + i * 16 + g;
#pragma unroll
            for (int j = 0; j < 4; j++) {
                int cb = wn * 32 + j * 8 + tig * 2;
                uint32_t* p0 = reinterpret_cast<uint32_t*>(Cb + (size_t)r0 * N + cb);
                uint32_t* p1 = reinterpret_cast<uint32_t*>(Cb + (size_t)(r0 + 8) * N + cb);
                p0[0] = f2tf32(acc[i][j][0]); p0[1] = f2tf32(acc[i][j][1]);
                p1[0] = f2tf32(acc[i][j][2]); p1[1] = f2tf32(acc[i][j][3]);
            }
        }
    } else {
#pragma unroll
        for (int i = 0; i < 4; i++) {
            int r0 = wm * 64 + i * 16 + g;
#pragma unroll
            for (int j = 0; j < 4; j++) {
                int cb = wn * 32 + j * 8 + tig * 2;
                *reinterpret_cast<float2*>(Cb + (size_t)r0 * N + cb) =
                    make_float2(acc[i][j][0], acc[i][j][1]);
                *reinterpret_cast<float2*>(Cb + (size_t)(r0 + 8) * N + cb) =
                    make_float2(acc[i][j][2], acc[i][j][3]);
            }
        }
    }
}

// ---------------- RMSNorm (merged q/kv; writes tf32-rounded) ----------------
__global__ __launch_bounds__(256) void rmsnorm2_kernel(
    float* __restrict__ xq, const float* __restrict__ wq,
    float* __restrict__ xkv, const float* __restrict__ wkv)
{
    __shared__ float red[8];
    const int row = blockIdx.x;
    float* xr;
    const float* w;
    int D;
    if (blockIdx.y == 0) { xr = xq + (size_t)row * QR; w = wq; D = QR; }
    else                 { xr = xkv + (size_t)row * KVR; w = wkv; D = KVR; }

    float ss = 0.f;
    for (int i = threadIdx.x; i < D; i += 256) {
        float v = xr[i];
        ss += v * v;
    }
#pragma unroll
    for (int o = 16; o > 0; o >>= 1) ss += __shfl_xor_sync(0xffffffffu, ss, o);
    int wid = threadIdx.x >> 5, lid = threadIdx.x & 31;
    if (lid == 0) red[wid] = ss;
    __syncthreads();
    if (wid == 0) {
        ss = (lid < 8) ? red[lid] : 0.f;
#pragma unroll
        for (int o = 4; o > 0; o >>= 1) ss += __shfl_xor_sync(0xffffffffu, ss, o);
        if (lid == 0) red[0] = ss;
    }
    __syncthreads();
    float inv = rsqrtf(red[0] / (float)D + RMS_EPS);
    for (int i = threadIdx.x; i < D; i += 256)
        reinterpret_cast<uint32_t*>(xr)[i] = f2tf32(w[i] * xr[i] * inv);
}

// ---------------- RoPE (values pre-rounded; writes rounded) ----------------
__global__ __launch_bounds__(256) void rope_kernel(float* q, float* k)
{
    int idx = blockIdx.x * blockDim.x + threadIdx.x;
    if (idx >= SEQ * NH * 32) return;
    int j = idx & 31;
    int h = (idx >> 5) & (NH - 1);
    int s = idx >> 9;

    float invf = powf(THETA, -(float)j / 32.0f);
    float ang = (float)s * invf;
    float sn, cs;
    sincosf(ang, &sn, &cs);

    float* qp = q + ((size_t)s * NH + h) * DQ + DN;
    float x1 = qp[j], x2 = qp[j + 32];
    reinterpret_cast<uint32_t*>(qp)[j]      = f2tf32(x1 * cs - x2 * sn);
    reinterpret_cast<uint32_t*>(qp)[j + 32] = f2tf32(x2 * cs + x1 * sn);

    float* kp = k + ((size_t)s * NH + h) * DQ + DN;
    x1 = kp[j]; x2 = kp[j + 32];
    reinterpret_cast<uint32_t*>(kp)[j]      = f2tf32(x1 * cs - x2 * sn);
    reinterpret_cast<uint32_t*>(kp)[j + 32] = f2tf32(x2 * cs + x1 * sn);
}

// ---------------- tensor-core flash attention v2 (unchanged, passing) ----------------
#define AQ 128
#define AK 32
#define QST 196
#define VST 136
#define QS_W (AQ * QST)
#define KS_W (AK * QST)
#define VS_W (AK * VST)
#define ATTN_SMEM ((QS_W + 2 * KS_W + 2 * VS_W) * 4)

__global__ __launch_bounds__(256) void attn_tf32_v2(
    const float* __restrict__ q, const float* __restrict__ kp,
    const float* __restrict__ vp, float* __restrict__ o)
{
    uint32_t* smem_u = reinterpret_cast<uint32_t*>(dsm);
    uint32_t* Qs = smem_u;
    uint32_t* Ks = smem_u + QS_W;
    uint32_t* Vs = Ks + 2 * KS_W;
    const uint32_t sbQ = (uint32_t)__cvta_generic_to_shared(Qs);
    const uint32_t sbK = (uint32_t)__cvta_generic_to_shared(Ks);
    const uint32_t sbV = (uint32_t)__cvta_generic_to_shared(Vs);

    const int qb = gridDim.x - 1 - blockIdx.x;
    const int h = blockIdx.y;
    const int tid = threadIdx.x;
    const int w = tid >> 5, lane = tid & 31;
    const int g = lane >> 2, tig = lane & 3;
    const int q0 = qb * AQ;
    const float scale = rsqrtf((float)DQ);

#define ISSUE_TILE(IT) do {                                                           \
        int _k0 = (IT) * AK; int _buf = (IT) & 1;                                     \
        _Pragma("unroll")                                                             \
        for (int _i = 0; _i < 6; _i++) {                                              \
            int _f = tid + _i * 256;                                                  \
            int _kr = _f / 48, _kc = _f % 48;                                         \
            cpa16(sbK + (_buf * KS_W + _kr * QST + _kc * 4) * 4,                      \
                  kp + ((size_t)(_k0 + _kr) * NH + h) * DQ + _kc * 4);                \
        }                                                                             \
        _Pragma("unroll")                                                             \
        for (int _i = 0; _i < 4; _i++) {                                              \
            int _f = tid + _i * 256;                                                  \
            int _vr = _f >> 5, _vc = _f & 31;                                         \
            cpa16(sbV + (_buf * VS_W + _vr * VST + _vc * 4) * 4,                      \
                  vp + ((size_t)(_k0 + _vr) * NH + h) * DV + _vc * 4);                \
        }                                                                             \
    } while (0)

    ISSUE_TILE(0);
    CP_COMMIT();

#pragma unroll
    for (int l = 0; l < 24; l++) {
        int f = tid + l * 256;
        int row = f / 48, c4 = (f % 48) * 4;
        float4 t4 = *reinterpret_cast<const float4*>(
            q + ((size_t)(q0 + row) * NH + h) * DQ + c4);
        uint4 u = make_uint4(f2tf32(t4.x * scale), f2tf32(t4.y * scale),
                             f2tf32(t4.z * scale), f2tf32(t4.w * scale));
        *reinterpret_cast<uint4*>(&Qs[row * QST + c4]) = u;
    }

    float oacc[16][4];
#pragma unroll
    for (int n = 0; n < 16; n++)
#pragma unroll
        for (int r = 0; r < 4; r++) oacc[n][r] = 0.f;
    float m0 = -1e30f, m1 = -1e30f, l0 = 0.f, l1 = 0.f;

    const uint32_t lmQ = sbQ + (((w * 16 + (lane & 15)) * QST + (lane >> 4) * 4) * 4);
    const uint32_t lmK = sbK + (((lane & 15) * QST + (lane >> 4) * 4) * 4);

    const int niter = (q0 + AQ) / AK;
    for (int it = 0; it < niter; it++) {
        const int k0g = it * AK;
        if (it + 1 < niter) ISSUE_TILE(it + 1);
        CP_COMMIT();
        CP_WAIT1();
        __syncthreads();

        const int buf = it & 1;
        const uint32_t lmK0 = lmK + buf * KS_W * 4;
        const uint32_t lmK1 = lmK0 + 16 * QST * 4;
        const uint32_t* fV = Vs + buf * VS_W + tig * VST + g;

        float s[4][4];
#pragma unroll
        for (int j = 0; j < 4; j++)
#pragma unroll
            for (int r = 0; r < 4; r++) s[j][r] = 0.f;

#pragma unroll
        for (int kt = 0; kt < 24; kt++) {
            uint32_t a0, a1, a2, a3, k00, k01, k02, k03, k10, k11, k12, k13;
            ldsm4(a0, a1, a2, a3, lmQ + kt * 32);
            ldsm4(k00, k01, k02, k03, lmK0 + kt * 32);
            ldsm4(k10, k11, k12, k13, lmK1 + kt * 32);
            mma_tf32(s[0][0], s[0][1], s[0][2], s[0][3], a0, a1, a2, a3, k00, k02);
            mma_tf32(s[1][0], s[1][1], s[1][2], s[1][3], a0, a1, a2, a3, k01, k03);
            mma_tf32(s[2][0], s[2][1], s[2][2], s[2][3], a0, a1, a2, a3, k10, k12);
            mma_tf32(s[3][0], s[3][1], s[3][2], s[3][3], a0, a1, a2, a3, k11, k13);
        }

        const int r0 = q0 + w * 16 + g, r1 = r0 + 8;
        if (k0g + AK - 1 > r0) {
#pragma unroll
            for (int j = 0; j < 4; j++) {
                int c0 = k0g + j * 8 + tig * 2, c1 = c0 + 1;
                if (c0 > r0) s[j][0] = -1e30f;
                if (c1 > r0) s[j][1] = -1e30f;
                if (c0 > r1) s[j][2] = -1e30f;
                if (c1 > r1) s[j][3] = -1e30f;
            }
        }

        float nm0 = -1e30f, nm1 = -1e30f;
#pragma unroll
        for (int j = 0; j < 4; j++) {
            nm0 = fmaxf(nm0, fmaxf(s[j][0], s[j][1]));
            nm1 = fmaxf(nm1, fmaxf(s[j][2], s[j][3]));
        }
        nm0 = fmaxf(nm0, __shfl_xor_sync(0xffffffffu, nm0, 1));
        nm0 = fmaxf(nm0, __shfl_xor_sync(0xffffffffu, nm0, 2));
        nm1 = fmaxf(nm1, __shfl_xor_sync(0xffffffffu, nm1, 1));
        nm1 = fmaxf(nm1, __shfl_xor_sync(0xffffffffu, nm1, 2));
        float mn0 = fmaxf(m0, nm0), mn1 = fmaxf(m1, nm1);
        float corr0 = fexp(m0 - mn0), corr1 = fexp(m1 - mn1);
        m0 = mn0; m1 = mn1;

        float rs0 = 0.f, rs1 = 0.f;
#pragma unroll
        for (int j = 0; j < 4; j++) {
            s[j][0] = fexp(s[j][0] - m0);
            s[j][1] = fexp(s[j][1] - m0);
            s[j][2] = fexp(s[j][2] - m1);
            s[j][3] = fexp(s[j][3] - m1);
            rs0 += s[j][0] + s[j][1];
            rs1 += s[j][2] + s[j][3];
        }
        rs0 += __shfl_xor_sync(0xffffffffu, rs0, 1);
        rs0 += __shfl_xor_sync(0xffffffffu, rs0, 2);
        rs1 += __shfl_xor_sync(0xffffffffu, rs1, 1);
        rs1 += __shfl_xor_sync(0xffffffffu, rs1, 2);
        l0 = l0 * corr0 + rs0;
        l1 = l1 * corr1 + rs1;

#pragma unroll
        for (int n = 0; n < 16; n++) {
            oacc[n][0] *= corr0; oacc[n][1] *= corr0;
            oacc[n][2] *= corr1; oacc[n][3] *= corr1;
        }

        const int src0 = (lane & 28) | (tig >> 1);
        const int src1 = src0 | 2;
        const bool bs = (tig & 1);
#pragma unroll
        for (int kt = 0; kt < 4; kt++) {
            float v00 = __shfl_sync(0xffffffffu, s[kt][0], src0);
            float v01 = __shfl_sync(0xffffffffu, s[kt][1], src0);
            float v10 = __shfl_sync(0xffffffffu, s[kt][2], src0);
            float v11 = __shfl_sync(0xffffffffu, s[kt][3], src0);
            float w00 = __shfl_sync(0xffffffffu, s[kt][0], src1);
            float w01 = __shfl_sync(0xffffffffu, s[kt][1], src1);
            float w10 = __shfl_sync(0xffffffffu, s[kt][2], src1);
            float w11 = __shfl_sync(0xffffffffu, s[kt][3], src1);
            float fa0 = bs ? v01 : v00;
            float fa1 = bs ? v11 : v10;
            float fa2 = bs ? w01 : w00;
            float fa3 = bs ? w11 : w10;
            uint32_t ah0 = f2tf32(fa0), ah1 = f2tf32(fa1);
            uint32_t ah2 = f2tf32(fa2), ah3 = f2tf32(fa3);
            uint32_t al0 = f2tf32(fa0 - __uint_as_float(ah0));
            uint32_t al1 = f2tf32(fa1 - __uint_as_float(ah1));
            uint32_t al2 = f2tf32(fa2 - __uint_as_float(ah2));
            uint32_t al3 = f2tf32(fa3 - __uint_as_float(ah3));
#pragma unroll
            for (int nt = 0; nt < 16; nt++) {
                uint32_t b0 = fV[kt * (8 * VST) + nt * 8];
                uint32_t b1 = fV[kt * (8 * VST) + 4 * VST + nt * 8];
                mma_tf32(oacc[nt][0], oacc[nt][1], oacc[nt][2], oacc[nt][3],
                         ah0, ah1, ah2, ah3, b0, b1);
                mma_tf32(oacc[nt][0], oacc[nt][1], oacc[nt][2], oacc[nt][3],
                         al0, al1, al2, al3, b0, b1);
            }
        }
        __syncthreads();
    }

    const float il0 = 1.0f / l0, il1 = 1.0f / l1;
    const int r0 = q0 + w * 16 + g, r1 = r0 + 8;
    uint32_t* o0 = reinterpret_cast<uint32_t*>(o + ((size_t)r0 * NH + h) * DV) + tig * 2;
    uint32_t* o1 = reinterpret_cast<uint32_t*>(o + ((size_t)r1 * NH + h) * DV) + tig * 2;
#pragma unroll
    for (int nt = 0; nt < 16; nt++) {
        o0[nt * 8]     = f2tf32(oacc[nt][0] * il0);
        o0[nt * 8 + 1] = f2tf32(oacc[nt][1] * il0);
        o1[nt * 8]     = f2tf32(oacc[nt][2] * il1);
        o1[nt * 8 + 1] = f2tf32(oacc[nt][3] * il1);
    }
#undef ISSUE_TILE
}

// ---------------- host launcher ----------------
extern "C" void kernel_launch(void* const* d_in, const int* in_sizes, int n_in,
                              void* d_out, int out_size)
{
    const float* x        = (const float*)d_in[0];
    const float* wq_down  = (const float*)d_in[1];
    const float* q_norm_w = (const float*)d_in[2];
    const float* wq_up    = (const float*)d_in[3];
    const float* wkv_down = (const float*)d_in[4];
    const float* kv_norm_w= (const float*)d_in[5];
    const float* wk_up    = (const float*)d_in[6];
    const float* wv_up    = (const float*)d_in[7];
    const float* wo       = (const float*)d_in[8];
    float* out = (float*)d_out;

    float *qlat, *qbuf, *kvlat, *kbuf, *vbuf, *attn;
    float *xr, *wqd, *wqu, *wkvd, *wku, *wvu, *wor;
    cudaGetSymbolAddress((void**)&qlat,  g_qlat);
    cudaGetSymbolAddress((void**)&qbuf,  g_q);
    cudaGetSymbolAddress((void**)&kvlat, g_kvlat);
    cudaGetSymbolAddress((void**)&kbuf,  g_k);
    cudaGetSymbolAddress((void**)&vbuf,  g_v);
    cudaGetSymbolAddress((void**)&attn,  g_attn);
    cudaGetSymbolAddress((void**)&xr,    g_xr);
    cudaGetSymbolAddress((void**)&wqd,   g_wqd);
    cudaGetSymbolAddress((void**)&wqu,   g_wqu);
    cudaGetSymbolAddress((void**)&wkvd,  g_wkvd);
    cudaGetSymbolAddress((void**)&wku,   g_wku);
    cudaGetSymbolAddress((void**)&wvu,   g_wvu);
    cudaGetSymbolAddress((void**)&wor,   g_wo);

    cudaFuncSetAttribute(sgemm_v8, cudaFuncAttributeMaxDynamicSharedMemorySize, GEMM_SMEM);
    cudaFuncSetAttribute(attn_tf32_v2, cudaFuncAttributeMaxDynamicSharedMemorySize, ATTN_SMEM);

    dim3 thr(256);
    dim3 t32(256);

    // prepass: round x; transpose+round weights
    round_x_kernel<<<(SEQ * H_DIM / 4 + 255) / 256, thr>>>(x);
    transpose_round_kernel<<<dim3(QR / 32, H_DIM / 32), t32>>>(wq_down,  wqd,  H_DIM, QR);
    transpose_round_kernel<<<dim3((NH * DQ) / 32, QR / 32), t32>>>(wq_up, wqu,  QR, NH * DQ);
    transpose_round_kernel<<<dim3(KVR / 32, H_DIM / 32), t32>>>(wkv_down, wkvd, H_DIM, KVR);
    transpose_round_kernel<<<dim3((NH * DQ) / 32, KVR / 32), t32>>>(wk_up, wku,  KVR, NH * DQ);
    transpose_round_kernel<<<dim3((NH * DV) / 32, KVR / 32), t32>>>(wv_up, wvu,  KVR, NH * DV);
    transpose_round_kernel<<<dim3(H_DIM / 32, (NH * DV) / 32), t32>>>(wo,   wor,  NH * DV, H_DIM);

    // down projections (merged). grid.x = 12 + 4 = 16
    sgemm_v8<<<dim3(16, SEQ / 128), thr, GEMM_SMEM>>>(
        xr, wqd, qlat, QR / 128, QR, H_DIM,
        xr, wkvd, kvlat, KVR / 128, KVR, H_DIM,
        xr, wkvd, kvlat, KVR, H_DIM,          // unused seg3
        0);

    rmsnorm2_kernel<<<dim3(SEQ, 2), thr>>>(qlat, q_norm_w, kvlat, kv_norm_w);

    // all up projections merged. grid.x = 24 + 24 + 16 = 64
    sgemm_v8<<<dim3(64, SEQ / 128), thr, GEMM_SMEM>>>(
        qlat,  wqu, qbuf, (NH * DQ) / 128, NH * DQ, QR,
        kvlat, wku, kbuf, (NH * DQ) / 128, NH * DQ, KVR,
        kvlat, wvu, vbuf, NH * DV, KVR,
        1);

    // rope (reads/writes rounded)
    rope_kernel<<<(SEQ * NH * 32) / 256, thr>>>(qbuf, kbuf);

    // causal attention, pipelined K/V
    attn_tf32_v2<<<dim3(SEQ / AQ, NH), thr, ATTN_SMEM>>>(qbuf, kbuf, vbuf, attn);

    // output projection (fp32 out). grid.x = 16
    sgemm_v8<<<dim3(16, SEQ / 128), thr, GEMM_SMEM>>>(
        attn, wor, out, H_DIM / 128, H_DIM, NH * DV,
        attn, wor, out, 0, H_DIM, NH * DV,    // unused seg2
        attn, wor, out, H_DIM, NH * DV,       // unused seg3
        0);
}

// round 15
// speedup vs baseline: 1.1169x; 1.1169x over previous
#include <cuda_runtime.h>
#include <math.h>
#include <stdint.h>

#define H_DIM 2048
#define NH 16
#define DN 128
#define DR 64
#define DQ 192
#define DV 128
#define KVR 512
#define QR 1536
#define SEQ 2048
#define THETA 100000.0f
#define RMS_EPS 1e-5f

// ---------------- scratch ----------------
__device__ float g_qlat[SEQ * QR];
__device__ float g_q[SEQ * NH * DQ];
__device__ float g_kvlat[SEQ * KVR];
__device__ float g_k[SEQ * NH * DQ];
__device__ float g_v[SEQ * NH * DV];
__device__ float g_attn[SEQ * NH * DV];
// pre-rounded (tf32) copies of inputs (K-major, same as R12)
__device__ float g_xr[SEQ * H_DIM];
__device__ float g_wqd[H_DIM * QR];
__device__ float g_wqu[QR * NH * DQ];
__device__ float g_wkvd[H_DIM * KVR];
__device__ float g_wku[KVR * NH * DQ];
__device__ float g_wvu[KVR * NH * DV];
__device__ float g_wo[NH * DV * H_DIM];

// ---------------- helpers ----------------
__device__ __forceinline__ uint32_t f2tf32(float v) {
    uint32_t u;
    asm("cvt.rna.tf32.f32 %0, %1;" : "=r"(u) : "f"(v));
    return u;
}

__device__ __forceinline__ void mma_tf32(
    float& c0, float& c1, float& c2, float& c3,
    uint32_t a0, uint32_t a1, uint32_t a2, uint32_t a3,
    uint32_t b0, uint32_t b1)
{
    asm volatile(
        "mma.sync.aligned.m16n8k8.row.col.f32.tf32.tf32.f32 "
        "{%0,%1,%2,%3}, {%4,%5,%6,%7}, {%8,%9}, {%0,%1,%2,%3};"
        : "+f"(c0), "+f"(c1), "+f"(c2), "+f"(c3)
        : "r"(a0), "r"(a1), "r"(a2), "r"(a3), "r"(b0), "r"(b1));
}

__device__ __forceinline__ void ldsm4(uint32_t& r0, uint32_t& r1, uint32_t& r2, uint32_t& r3,
                                      uint32_t saddr)
{
    asm volatile("ldmatrix.sync.aligned.m8n8.x4.shared.b16 {%0,%1,%2,%3}, [%4];"
                 : "=r"(r0), "=r"(r1), "=r"(r2), "=r"(r3) : "r"(saddr));
}

__device__ __forceinline__ void cpa16(uint32_t saddr, const void* g) {
    asm volatile("cp.async.cg.shared.global [%0], [%1], 16;" :: "r"(saddr), "l"(g));
}
#define CP_COMMIT() asm volatile("cp.async.commit_group;")
#define CP_WAITG1() asm volatile("cp.async.wait_group 1;")
#define CP_WAIT1()  asm volatile("cp.async.wait_group 1;")

// fast exp on FMA pipe
__device__ __forceinline__ float fexp(float x) {
    x = fmaxf(x, -80.f) * 1.4426950408889634f;
    float z = x + 12582912.f;
    int n = __float_as_int(z) - 0x4B400000;
    float f = x - (z - 12582912.f);
    float p = 1.3333558146e-3f;
    p = fmaf(p, f, 9.6180209e-3f);
    p = fmaf(p, f, 5.5504109e-2f);
    p = fmaf(p, f, 2.4022651e-1f);
    p = fmaf(p, f, 6.9314718e-1f);
    p = fmaf(p, f, 1.0f);
    return p * __int_as_float((n + 127) << 23);
}

// ---------------- tf32 prepass: single launch, 7 segments ----------------
#define RN0 (SEQ * H_DIM / 4)
#define RN1 (RN0 + H_DIM * QR / 4)
#define RN2 (RN1 + QR * NH * DQ / 4)
#define RN3 (RN2 + H_DIM * KVR / 4)
#define RN4 (RN3 + KVR * NH * DQ / 4)
#define RN5 (RN4 + KVR * NH * DV / 4)
#define RN6 (RN5 + NH * DV * H_DIM / 4)

__global__ __launch_bounds__(256) void round_all_kernel(
    const float* __restrict__ x, const float* __restrict__ wqd_s,
    const float* __restrict__ wqu_s, const float* __restrict__ wkvd_s,
    const float* __restrict__ wku_s, const float* __restrict__ wvu_s,
    const float* __restrict__ wo_s)
{
    int i = blockIdx.x * 256 + threadIdx.x;
    if (i >= RN6) return;
    const float* src;
    float* dst;
    int off;
    if      (i < RN0) { src = x;      dst = g_xr;   off = i; }
    else if (i < RN1) { src = wqd_s;  dst = g_wqd;  off = i - RN0; }
    else if (i < RN2) { src = wqu_s;  dst = g_wqu;  off = i - RN1; }
    else if (i < RN3) { src = wkvd_s; dst = g_wkvd; off = i - RN2; }
    else if (i < RN4) { src = wku_s;  dst = g_wku;  off = i - RN3; }
    else if (i < RN5) { src = wvu_s;  dst = g_wvu;  off = i - RN4; }
    else              { src = wo_s;   dst = g_wo;   off = i - RN5; }
    float4 t = reinterpret_cast<const float4*>(src)[off];
    uint4 u = make_uint4(f2tf32(t.x), f2tf32(t.y), f2tf32(t.z), f2tf32(t.w));
    reinterpret_cast<uint4*>(dst)[off] = u;
}

// ---- tf32 GEMM v9: 5-stage cp.async, barrier/2-iters, frag double-buffer ----
#define AST 20
#define BST 136
#define ASZ (128 * AST)
#define BSZ (16 * BST)
#define STAGES 5
#define GEMM_SMEM ((STAGES * (ASZ + BSZ)) * 4)

extern __shared__ float dsm[];

__global__ __launch_bounds__(256, 2) void sgemm_tf32_v9(
    const float* __restrict__ A1, const float* __restrict__ B1, float* __restrict__ C1,
    int nb1, int N1, int K1,
    const float* __restrict__ A2, const float* __restrict__ B2, float* __restrict__ C2,
    int nb2, int N2, int K2,
    const float* __restrict__ A3, const float* __restrict__ B3, float* __restrict__ C3,
    int N3, int K3,
    int roundC)
{
    float* Asf = dsm;
    float* Bsf = dsm + STAGES * ASZ;
    const uint32_t sbA = (uint32_t)__cvta_generic_to_shared(Asf);
    const uint32_t sbB = (uint32_t)__cvta_generic_to_shared(Bsf);

    int bx = blockIdx.x;
    const int by = blockIdx.y;
    const float* A;
    const float* B;
    float* C;
    int N, K;
    if (bx < nb1)            { A = A1; B = B1; C = C1; N = N1; K = K1; }
    else if (bx < nb1 + nb2) { A = A2; B = B2; C = C2; N = N2; K = K2; bx -= nb1; }
    else                     { A = A3; B = B3; C = C3; N = N3; K = K3; bx -= nb1 + nb2; }

    const int tid = threadIdx.x;
    const int wid = tid >> 5, lane = tid & 31;
    const int g = lane >> 2, tig = lane & 3;
    const int wm = wid & 1, wn = wid >> 1;

    const int am = tid >> 2, ak4 = (tid & 3) * 4;
    const int bk = tid >> 5, bn4 = (tid & 31) * 4;
    const float* pA0 = A + (size_t)(by * 128 + am) * K + ak4;
    const float* pA1 = pA0 + (size_t)64 * K;
    const float* pB0 = B + (size_t)bk * N + bx * 128 + bn4;
    const float* pB1 = pB0 + (size_t)8 * N;

    const uint32_t saA0 = sbA + (am * AST + ak4) * 4;
    const uint32_t saA1 = sbA + ((am + 64) * AST + ak4) * 4;
    const uint32_t saB0 = sbB + (bk * BST + bn4) * 4;
    const uint32_t saB1 = sbB + ((bk + 8) * BST + bn4) * 4;

    const uint32_t lmA = sbA + (((wm * 64 + (lane & 15)) * AST + (lane >> 4) * 4) * 4);
    const uint32_t* fB = reinterpret_cast<const uint32_t*>(Bsf) + wn * 32 + g + tig * BST;

    float acc[4][4][4];
#pragma unroll
    for (int i = 0; i < 4; i++)
#pragma unroll
        for (int j = 0; j < 4; j++)
#pragma unroll
            for (int r = 0; r < 4; r++) acc[i][j][r] = 0.f;

    const int nt = K >> 4;

#define GEMM_ISSUE(T) do {                                                    \
        if ((T) < nt) {                                                       \
            int _s = (T) % STAGES;                                            \
            int _k0 = (T) * 16;                                               \
            cpa16(saA0 + _s * ASZ * 4, pA0 + _k0);                            \
            cpa16(saA1 + _s * ASZ * 4, pA1 + _k0);                            \
            cpa16(saB0 + _s * BSZ * 4, pB0 + (size_t)_k0 * N);                \
            cpa16(saB1 + _s * BSZ * 4, pB1 + (size_t)_k0 * N);                \
        }                                                                     \
        CP_COMMIT();                                                          \
    } while (0)

    // fragment batch load: slot SLOT, k-offset KK -> FA[4][4], FBB[4][2]
#define LOAD_FRAGS(FA, FBB, SLOT, KK) do {                                    \
        const uint32_t _lA = lmA + ((SLOT) * ASZ + (KK)) * 4;                 \
        const uint32_t* _cB = fB + (SLOT) * BSZ + (KK) * BST;                 \
        _Pragma("unroll")                                                     \
        for (int i = 0; i < 4; i++)                                           \
            ldsm4(FA[i][0], FA[i][1], FA[i][2], FA[i][3],                     \
                  _lA + (i * 16 * AST) * 4);                                  \
        _Pragma("unroll")                                                     \
        for (int j = 0; j < 4; j++) {                                         \
            FBB[j][0] = _cB[j * 8];                                           \
            FBB[j][1] = _cB[4 * BST + j * 8];                                 \
        }                                                                     \
    } while (0)

#define DO_MMAS(FA, FBB) do {                                                 \
        _Pragma("unroll")                                                     \
        for (int i = 0; i < 4; i++)                                           \
            _Pragma("unroll")                                                 \
            for (int j = 0; j < 4; j++)                                       \
                mma_tf32(acc[i][j][0], acc[i][j][1], acc[i][j][2],            \
                         acc[i][j][3], FA[i][0], FA[i][1], FA[i][2],          \
                         FA[i][3], FBB[j][0], FBB[j][1]);                     \
    } while (0)

    GEMM_ISSUE(0);
    GEMM_ISSUE(1);
    GEMM_ISSUE(2);

    uint32_t fa0[4][4], fb0[4][2], fa1[4][4], fb1[4][2];

    // nt is even for all shapes used (16, 32, 96, 128)
    for (int it = 0; it < nt; it += 2) {
        CP_WAITG1();            // tiles it, it+1 resident (only it+2 pending)
        __syncthreads();        // WAR on slots being refilled

        const int s0 = it % STAGES, s1 = (it + 1) % STAGES;

        GEMM_ISSUE(it + 3);
        LOAD_FRAGS(fa0, fb0, s0, 0);
        LOAD_FRAGS(fa1, fb1, s0, 8);
        DO_MMAS(fa0, fb0);
        LOAD_FRAGS(fa0, fb0, s1, 0);
        GEMM_ISSUE(it + 4);
        DO_MMAS(fa1, fb1);
        LOAD_FRAGS(fa1, fb1, s1, 8);
        DO_MMAS(fa0, fb0);
        DO_MMAS(fa1, fb1);
    }
#undef GEMM_ISSUE
#undef LOAD_FRAGS
#undef DO_MMAS

    float* Cb = C + (size_t)(by * 128) * N + bx * 128;
    if (roundC) {
#pragma unroll
        for (int i = 0; i < 4; i++) {
            int r0 = wm * 64 + i * 16 + g;
#pragma unroll
            for (int j = 0; j < 4; j++) {
                int cb = wn * 32 + j * 8 + tig * 2;
                uint32_t* p0 = reinterpret_cast<uint32_t*>(Cb + (size_t)r0 * N + cb);
                uint32_t* p1 = reinterpret_cast<uint32_t*>(Cb + (size_t)(r0 + 8) * N + cb);
                p0[0] = f2tf32(acc[i][j][0]); p0[1] = f2tf32(acc[i][j][1]);
                p1[0] = f2tf32(acc[i][j][2]); p1[1] = f2tf32(acc[i][j][3]);
            }
        }
    } else {
#pragma unroll
        for (int i = 0; i < 4; i++) {
            int r0 = wm * 64 + i * 16 + g;
#pragma unroll
            for (int j = 0; j < 4; j++) {
                int cb = wn * 32 + j * 8 + tig * 2;
                *reinterpret_cast<float2*>(Cb + (size_t)r0 * N + cb) =
                    make_float2(acc[i][j][0], acc[i][j][1]);
                *reinterpret_cast<float2*>(Cb + (size_t)(r0 + 8) * N + cb) =
                    make_float2(acc[i][j][2], acc[i][j][3]);
            }
        }
    }
}

// ---------------- RMSNorm (merged q/kv; writes tf32-rounded) ----------------
__global__ __launch_bounds__(256) void rmsnorm2_kernel(
    float* __restrict__ xq, const float* __restrict__ wq,
    float* __restrict__ xkv, const float* __restrict__ wkv)
{
    __shared__ float red[8];
    const int row = blockIdx.x;
    float* xr;
    const float* w;
    int D;
    if (blockIdx.y == 0) { xr = xq + (size_t)row * QR; w = wq; D = QR; }
    else                 { xr = xkv + (size_t)row * KVR; w = wkv; D = KVR; }

    float ss = 0.f;
    for (int i = threadIdx.x; i < D; i += 256) {
        float v = xr[i];
        ss += v * v;
    }
#pragma unroll
    for (int o = 16; o > 0; o >>= 1) ss += __shfl_xor_sync(0xffffffffu, ss, o);
    int wid = threadIdx.x >> 5, lid = threadIdx.x & 31;
    if (lid == 0) red[wid] = ss;
    __syncthreads();
    if (wid == 0) {
        ss = (lid < 8) ? red[lid] : 0.f;
#pragma unroll
        for (int o = 4; o > 0; o >>= 1) ss += __shfl_xor_sync(0xffffffffu, ss, o);
        if (lid == 0) red[0] = ss;
    }
    __syncthreads();
    float inv = rsqrtf(red[0] / (float)D + RMS_EPS);
    for (int i = threadIdx.x; i < D; i += 256)
        reinterpret_cast<uint32_t*>(xr)[i] = f2tf32(w[i] * xr[i] * inv);
}

// ---------------- RoPE (values pre-rounded; writes rounded) ----------------
__global__ __launch_bounds__(256) void rope_kernel(float* q, float* k)
{
    int idx = blockIdx.x * blockDim.x + threadIdx.x;
    if (idx >= SEQ * NH * 32) return;
    int j = idx & 31;
    int h = (idx >> 5) & (NH - 1);
    int s = idx >> 9;

    float invf = powf(THETA, -(float)j / 32.0f);
    float ang = (float)s * invf;
    float sn, cs;
    sincosf(ang, &sn, &cs);

    float* qp = q + ((size_t)s * NH + h) * DQ + DN;
    float x1 = qp[j], x2 = qp[j + 32];
    reinterpret_cast<uint32_t*>(qp)[j]      = f2tf32(x1 * cs - x2 * sn);
    reinterpret_cast<uint32_t*>(qp)[j + 32] = f2tf32(x2 * cs + x1 * sn);

    float* kp = k + ((size_t)s * NH + h) * DQ + DN;
    x1 = kp[j]; x2 = kp[j + 32];
    reinterpret_cast<uint32_t*>(kp)[j]      = f2tf32(x1 * cs - x2 * sn);
    reinterpret_cast<uint32_t*>(kp)[j + 32] = f2tf32(x2 * cs + x1 * sn);
}

// ---------------- tensor-core flash attention v2 (unchanged, passing) ----------------
#define AQ 128
#define AK 32
#define QST 196
#define VST 136
#define QS_W (AQ * QST)
#define KS_W (AK * QST)
#define VS_W (AK * VST)
#define ATTN_SMEM ((QS_W + 2 * KS_W + 2 * VS_W) * 4)

__global__ __launch_bounds__(256) void attn_tf32_v2(
    const float* __restrict__ q, const float* __restrict__ kp,
    const float* __restrict__ vp, float* __restrict__ o)
{
    uint32_t* smem_u = reinterpret_cast<uint32_t*>(dsm);
    uint32_t* Qs = smem_u;
    uint32_t* Ks = smem_u + QS_W;
    uint32_t* Vs = Ks + 2 * KS_W;
    const uint32_t sbQ = (uint32_t)__cvta_generic_to_shared(Qs);
    const uint32_t sbK = (uint32_t)__cvta_generic_to_shared(Ks);
    const uint32_t sbV = (uint32_t)__cvta_generic_to_shared(Vs);

    const int qb = gridDim.x - 1 - blockIdx.x;
    const int h = blockIdx.y;
    const int tid = threadIdx.x;
    const int w = tid >> 5, lane = tid & 31;
    const int g = lane >> 2, tig = lane & 3;
    const int q0 = qb * AQ;
    const float scale = rsqrtf((float)DQ);

#define ISSUE_TILE(IT) do {                                                           \
        int _k0 = (IT) * AK; int _buf = (IT) & 1;                                     \
        _Pragma("unroll")                                                             \
        for (int _i = 0; _i < 6; _i++) {                                              \
            int _f = tid + _i * 256;                                                  \
            int _kr = _f / 48, _kc = _f % 48;                                         \
            cpa16(sbK + (_buf * KS_W + _kr * QST + _kc * 4) * 4,                      \
                  kp + ((size_t)(_k0 + _kr) * NH + h) * DQ + _kc * 4);                \
        }                                                                             \
        _Pragma("unroll")                                                             \
        for (int _i = 0; _i < 4; _i++) {                                              \
            int _f = tid + _i * 256;                                                  \
            int _vr = _f >> 5, _vc = _f & 31;                                         \
            cpa16(sbV + (_buf * VS_W + _vr * VST + _vc * 4) * 4,                      \
                  vp + ((size_t)(_k0 + _vr) * NH + h) * DV + _vc * 4);                \
        }                                                                             \
    } while (0)

    ISSUE_TILE(0);
    CP_COMMIT();

#pragma unroll
    for (int l = 0; l < 24; l++) {
        int f = tid + l * 256;
        int row = f / 48, c4 = (f % 48) * 4;
        float4 t4 = *reinterpret_cast<const float4*>(
            q + ((size_t)(q0 + row) * NH + h) * DQ + c4);
        uint4 u = make_uint4(f2tf32(t4.x * scale), f2tf32(t4.y * scale),
                             f2tf32(t4.z * scale), f2tf32(t4.w * scale));
        *reinterpret_cast<uint4*>(&Qs[row * QST + c4]) = u;
    }

    float oacc[16][4];
#pragma unroll
    for (int n = 0; n < 16; n++)
#pragma unroll
        for (int r = 0; r < 4; r++) oacc[n][r] = 0.f;
    float m0 = -1e30f, m1 = -1e30f, l0 = 0.f, l1 = 0.f;

    const uint32_t lmQ = sbQ + (((w * 16 + (lane & 15)) * QST + (lane >> 4) * 4) * 4);
    const uint32_t lmK = sbK + (((lane & 15) * QST + (lane >> 4) * 4) * 4);

    const int niter = (q0 + AQ) / AK;
    for (int it = 0; it < niter; it++) {
        const int k0g = it * AK;
        if (it + 1 < niter) ISSUE_TILE(it + 1);
        CP_COMMIT();
        CP_WAIT1();
        __syncthreads();

        const int buf = it & 1;
        const uint32_t lmK0 = lmK + buf * KS_W * 4;
        const uint32_t lmK1 = lmK0 + 16 * QST * 4;
        const uint32_t* fV = Vs + buf * VS_W + tig * VST + g;

        float s[4][4];
#pragma unroll
        for (int j = 0; j < 4; j++)
#pragma unroll
            for (int r = 0; r < 4; r++) s[j][r] = 0.f;

#pragma unroll
        for (int kt = 0; kt < 24; kt++) {
            uint32_t a0, a1, a2, a3, k00, k01, k02, k03, k10, k11, k12, k13;
            ldsm4(a0, a1, a2, a3, lmQ + kt * 32);
            ldsm4(k00, k01, k02, k03, lmK0 + kt * 32);
            ldsm4(k10, k11, k12, k13, lmK1 + kt * 32);
            mma_tf32(s[0][0], s[0][1], s[0][2], s[0][3], a0, a1, a2, a3, k00, k02);
            mma_tf32(s[1][0], s[1][1], s[1][2], s[1][3], a0, a1, a2, a3, k01, k03);
            mma_tf32(s[2][0], s[2][1], s[2][2], s[2][3], a0, a1, a2, a3, k10, k12);
            mma_tf32(s[3][0], s[3][1], s[3][2], s[3][3], a0, a1, a2, a3, k11, k13);
        }

        const int r0 = q0 + w * 16 + g, r1 = r0 + 8;
        if (k0g + AK - 1 > r0) {
#pragma unroll
            for (int j = 0; j < 4; j++) {
                int c0 = k0g + j * 8 + tig * 2, c1 = c0 + 1;
                if (c0 > r0) s[j][0] = -1e30f;
                if (c1 > r0) s[j][1] = -1e30f;
                if (c0 > r1) s[j][2] = -1e30f;
                if (c1 > r1) s[j][3] = -1e30f;
            }
        }

        float nm0 = -1e30f, nm1 = -1e30f;
#pragma unroll
        for (int j = 0; j < 4; j++) {
            nm0 = fmaxf(nm0, fmaxf(s[j][0], s[j][1]));
            nm1 = fmaxf(nm1, fmaxf(s[j][2], s[j][3]));
        }
        nm0 = fmaxf(nm0, __shfl_xor_sync(0xffffffffu, nm0, 1));
        nm0 = fmaxf(nm0, __shfl_xor_sync(0xffffffffu, nm0, 2));
        nm1 = fmaxf(nm1, __shfl_xor_sync(0xffffffffu, nm1, 1));
        nm1 = fmaxf(nm1, __shfl_xor_sync(0xffffffffu, nm1, 2));
        float mn0 = fmaxf(m0, nm0), mn1 = fmaxf(m1, nm1);
        float corr0 = fexp(m0 - mn0), corr1 = fexp(m1 - mn1);
        m0 = mn0; m1 = mn1;

        float rs0 = 0.f, rs1 = 0.f;
#pragma unroll
        for (int j = 0; j < 4; j++) {
            s[j][0] = fexp(s[j][0] - m0);
            s[j][1] = fexp(s[j][1] - m0);
            s[j][2] = fexp(s[j][2] - m1);
            s[j][3] = fexp(s[j][3] - m1);
            rs0 += s[j][0] + s[j][1];
            rs1 += s[j][2] + s[j][3];
        }
        rs0 += __shfl_xor_sync(0xffffffffu, rs0, 1);
        rs0 += __shfl_xor_sync(0xffffffffu, rs0, 2);
        rs1 += __shfl_xor_sync(0xffffffffu, rs1, 1);
        rs1 += __shfl_xor_sync(0xffffffffu, rs1, 2);
        l0 = l0 * corr0 + rs0;
        l1 = l1 * corr1 + rs1;

#pragma unroll
        for (int n = 0; n < 16; n++) {
            oacc[n][0] *= corr0; oacc[n][1] *= corr0;
            oacc[n][2] *= corr1; oacc[n][3] *= corr1;
        }

        const int src0 = (lane & 28) | (tig >> 1);
        const int src1 = src0 | 2;
        const bool bs = (tig & 1);
#pragma unroll
        for (int kt = 0; kt < 4; kt++) {
            float v00 = __shfl_sync(0xffffffffu, s[kt][0], src0);
            float v01 = __shfl_sync(0xffffffffu, s[kt][1], src0);
            float v10 = __shfl_sync(0xffffffffu, s[kt][2], src0);
            float v11 = __shfl_sync(0xffffffffu, s[kt][3], src0);
            float w00 = __shfl_sync(0xffffffffu, s[kt][0], src1);
            float w01 = __shfl_sync(0xffffffffu, s[kt][1], src1);
            float w10 = __shfl_sync(0xffffffffu, s[kt][2], src1);
            float w11 = __shfl_sync(0xffffffffu, s[kt][3], src1);
            float fa0 = bs ? v01 : v00;
            float fa1 = bs ? v11 : v10;
            float fa2 = bs ? w01 : w00;
            float fa3 = bs ? w11 : w10;
            uint32_t ah0 = f2tf32(fa0), ah1 = f2tf32(fa1);
            uint32_t ah2 = f2tf32(fa2), ah3 = f2tf32(fa3);
            uint32_t al0 = f2tf32(fa0 - __uint_as_float(ah0));
            uint32_t al1 = f2tf32(fa1 - __uint_as_float(ah1));
            uint32_t al2 = f2tf32(fa2 - __uint_as_float(ah2));
            uint32_t al3 = f2tf32(fa3 - __uint_as_float(ah3));
#pragma unroll
            for (int nt = 0; nt < 16; nt++) {
                uint32_t b0 = fV[kt * (8 * VST) + nt * 8];
                uint32_t b1 = fV[kt * (8 * VST) + 4 * VST + nt * 8];
                mma_tf32(oacc[nt][0], oacc[nt][1], oacc[nt][2], oacc[nt][3],
                         ah0, ah1, ah2, ah3, b0, b1);
                mma_tf32(oacc[nt][0], oacc[nt][1], oacc[nt][2], oacc[nt][3],
                         al0, al1, al2, al3, b0, b1);
            }
        }
        __syncthreads();
    }

    const float il0 = 1.0f / l0, il1 = 1.0f / l1;
    const int r0 = q0 + w * 16 + g, r1 = r0 + 8;
    uint32_t* o0 = reinterpret_cast<uint32_t*>(o + ((size_t)r0 * NH + h) * DV) + tig * 2;
    uint32_t* o1 = reinterpret_cast<uint32_t*>(o + ((size_t)r1 * NH + h) * DV) + tig * 2;
#pragma unroll
    for (int nt = 0; nt < 16; nt++) {
        o0[nt * 8]     = f2tf32(oacc[nt][0] * il0);
        o0[nt * 8 + 1] = f2tf32(oacc[nt][1] * il0);
        o1[nt * 8]     = f2tf32(oacc[nt][2] * il1);
        o1[nt * 8 + 1] = f2tf32(oacc[nt][3] * il1);
    }
#undef ISSUE_TILE
}

// ---------------- host launcher ----------------
extern "C" void kernel_launch(void* const* d_in, const int* in_sizes, int n_in,
                              void* d_out, int out_size)
{
    const float* x        = (const float*)d_in[0];
    const float* wq_down  = (const float*)d_in[1];
    const float* q_norm_w = (const float*)d_in[2];
    const float* wq_up    = (const float*)d_in[3];
    const float* wkv_down = (const float*)d_in[4];
    const float* kv_norm_w= (const float*)d_in[5];
    const float* wk_up    = (const float*)d_in[6];
    const float* wv_up    = (const float*)d_in[7];
    const float* wo       = (const float*)d_in[8];
    float* out = (float*)d_out;

    float *qlat, *qbuf, *kvlat, *kbuf, *vbuf, *attn;
    float *xr, *wqd, *wqu, *wkvd, *wku, *wvu, *wor;
    cudaGetSymbolAddress((void**)&qlat,  g_qlat);
    cudaGetSymbolAddress((void**)&qbuf,  g_q);
    cudaGetSymbolAddress((void**)&kvlat, g_kvlat);
    cudaGetSymbolAddress((void**)&kbuf,  g_k);
    cudaGetSymbolAddress((void**)&vbuf,  g_v);
    cudaGetSymbolAddress((void**)&attn,  g_attn);
    cudaGetSymbolAddress((void**)&xr,    g_xr);
    cudaGetSymbolAddress((void**)&wqd,   g_wqd);
    cudaGetSymbolAddress((void**)&wqu,   g_wqu);
    cudaGetSymbolAddress((void**)&wkvd,  g_wkvd);
    cudaGetSymbolAddress((void**)&wku,   g_wku);
    cudaGetSymbolAddress((void**)&wvu,   g_wvu);
    cudaGetSymbolAddress((void**)&wor,   g_wo);

    cudaFuncSetAttribute(sgemm_tf32_v9, cudaFuncAttributeMaxDynamicSharedMemorySize, GEMM_SMEM);
    cudaFuncSetAttribute(attn_tf32_v2, cudaFuncAttributeMaxDynamicSharedMemorySize, ATTN_SMEM);

    dim3 thr(256);

    // prepass: round x + all weights to tf32 (single launch)
    round_all_kernel<<<(RN6 + 255) / 256, thr>>>(
        x, wq_down, wq_up, wkv_down, wk_up, wv_up, wo);

    // down projections (merged). grid.x = 12 + 4 = 16
    sgemm_tf32_v9<<<dim3(16, SEQ / 128), thr, GEMM_SMEM>>>(
        xr, wqd, qlat, QR / 128, QR, H_DIM,
        xr, wkvd, kvlat, KVR / 128, KVR, H_DIM,
        xr, wkvd, kvlat, KVR, H_DIM,          // unused seg3
        0);

    rmsnorm2_kernel<<<dim3(SEQ, 2), thr>>>(qlat, q_norm_w, kvlat, kv_norm_w);

    // all up projections merged. grid.x = 24 + 24 + 16 = 64
    sgemm_tf32_v9<<<dim3(64, SEQ / 128), thr, GEMM_SMEM>>>(
        qlat,  wqu, qbuf, (NH * DQ) / 128, NH * DQ, QR,
        kvlat, wku, kbuf, (NH * DQ) / 128, NH * DQ, KVR,
        kvlat, wvu, vbuf, NH * DV, KVR,
        1);

    // rope (reads/writes rounded)
    rope_kernel<<<(SEQ * NH * 32) / 256, thr>>>(qbuf, kbuf);

    // causal attention, pipelined K/V
    attn_tf32_v2<<<dim3(SEQ / AQ, NH), thr, ATTN_SMEM>>>(qbuf, kbuf, vbuf, attn);

    // output projection (fp32 out). grid.x = 16
    sgemm_tf32_v9<<<dim3(16, SEQ / 128), thr, GEMM_SMEM>>>(
        attn, wor, out, H_DIM / 128, H_DIM, NH * DV,
        attn, wor, out, 0, H_DIM, NH * DV,    // unused seg2
        attn, wor, out, H_DIM, NH * DV,       // unused seg3
        0);
}

// round 16
// speedup vs baseline: 1.1952x; 1.0701x over previous
#include <cuda_runtime.h>
#include <math.h>
#include <stdint.h>

#define H_DIM 2048
#define NH 16
#define DN 128
#define DR 64
#define DQ 192
#define DV 128
#define KVR 512
#define QR 1536
#define SEQ 2048
#define THETA 100000.0f
#define RMS_EPS 1e-5f

// ---------------- scratch ----------------
__device__ float g_qlat[SEQ * QR];
__device__ float g_q[SEQ * NH * DQ];
__device__ float g_kvlat[SEQ * KVR];
__device__ float g_k[SEQ * NH * DQ];
__device__ float g_v[SEQ * NH * DV];
__device__ float g_attn[SEQ * NH * DV];
// pre-rounded (tf32) copies of inputs
__device__ float g_xr[SEQ * H_DIM];
__device__ float g_wqd[H_DIM * QR];
__device__ float g_wqu[QR * NH * DQ];
__device__ float g_wkvd[H_DIM * KVR];
__device__ float g_wku[KVR * NH * DQ];
__device__ float g_wvu[KVR * NH * DV];
__device__ float g_wo[NH * DV * H_DIM];

// ---------------- helpers ----------------
__device__ __forceinline__ uint32_t f2tf32(float v) {
    uint32_t u;
    asm("cvt.rna.tf32.f32 %0, %1;" : "=r"(u) : "f"(v));
    return u;
}

__device__ __forceinline__ void mma_tf32(
    float& c0, float& c1, float& c2, float& c3,
    uint32_t a0, uint32_t a1, uint32_t a2, uint32_t a3,
    uint32_t b0, uint32_t b1)
{
    asm volatile(
        "mma.sync.aligned.m16n8k8.row.col.f32.tf32.tf32.f32 "
        "{%0,%1,%2,%3}, {%4,%5,%6,%7}, {%8,%9}, {%0,%1,%2,%3};"
        : "+f"(c0), "+f"(c1), "+f"(c2), "+f"(c3)
        : "r"(a0), "r"(a1), "r"(a2), "r"(a3), "r"(b0), "r"(b1));
}

__device__ __forceinline__ void ldsm4(uint32_t& r0, uint32_t& r1, uint32_t& r2, uint32_t& r3,
                                      uint32_t saddr)
{
    asm volatile("ldmatrix.sync.aligned.m8n8.x4.shared.b16 {%0,%1,%2,%3}, [%4];"
                 : "=r"(r0), "=r"(r1), "=r"(r2), "=r"(r3) : "r"(saddr));
}

__device__ __forceinline__ void cpa16(uint32_t saddr, const void* g) {
    asm volatile("cp.async.cg.shared.global [%0], [%1], 16;" :: "r"(saddr), "l"(g));
}
#define CP_COMMIT() asm volatile("cp.async.commit_group;")
#define CP_WAITG1() asm volatile("cp.async.wait_group 1;")
#define CP_WAIT1()  asm volatile("cp.async.wait_group 1;")

// fast exp on FMA pipe
__device__ __forceinline__ float fexp(float x) {
    x = fmaxf(x, -80.f) * 1.4426950408889634f;
    float z = x + 12582912.f;
    int n = __float_as_int(z) - 0x4B400000;
    float f = x - (z - 12582912.f);
    float p = 1.3333558146e-3f;
    p = fmaf(p, f, 9.6180209e-3f);
    p = fmaf(p, f, 5.5504109e-2f);
    p = fmaf(p, f, 2.4022651e-1f);
    p = fmaf(p, f, 6.9314718e-1f);
    p = fmaf(p, f, 1.0f);
    return p * __int_as_float((n + 127) << 23);
}

// ---------------- tf32 prepass: single launch, 7 segments ----------------
#define RN0 (SEQ * H_DIM / 4)
#define RN1 (RN0 + H_DIM * QR / 4)
#define RN2 (RN1 + QR * NH * DQ / 4)
#define RN3 (RN2 + H_DIM * KVR / 4)
#define RN4 (RN3 + KVR * NH * DQ / 4)
#define RN5 (RN4 + KVR * NH * DV / 4)
#define RN6 (RN5 + NH * DV * H_DIM / 4)

__global__ __launch_bounds__(256) void round_all_kernel(
    const float* __restrict__ x, const float* __restrict__ wqd_s,
    const float* __restrict__ wqu_s, const float* __restrict__ wkvd_s,
    const float* __restrict__ wku_s, const float* __restrict__ wvu_s,
    const float* __restrict__ wo_s)
{
    int i = blockIdx.x * 256 + threadIdx.x;
    if (i >= RN6) return;
    const float* src;
    float* dst;
    int off;
    if      (i < RN0) { src = x;      dst = g_xr;   off = i; }
    else if (i < RN1) { src = wqd_s;  dst = g_wqd;  off = i - RN0; }
    else if (i < RN2) { src = wqu_s;  dst = g_wqu;  off = i - RN1; }
    else if (i < RN3) { src = wkvd_s; dst = g_wkvd; off = i - RN2; }
    else if (i < RN4) { src = wku_s;  dst = g_wku;  off = i - RN3; }
    else if (i < RN5) { src = wvu_s;  dst = g_wvu;  off = i - RN4; }
    else              { src = wo_s;   dst = g_wo;   off = i - RN5; }
    float4 t = reinterpret_cast<const float4*>(src)[off];
    uint4 u = make_uint4(f2tf32(t.x), f2tf32(t.y), f2tf32(t.z), f2tf32(t.w));
    reinterpret_cast<uint4*>(dst)[off] = u;
}

// ---- tf32 GEMM v9: 5-stage cp.async, barrier/2-iters, frag double-buffer ----
#define AST 20
#define BST 136
#define ASZ (128 * AST)
#define BSZ (16 * BST)
#define STAGES 5
#define GEMM_SMEM ((STAGES * (ASZ + BSZ)) * 4)

extern __shared__ float dsm[];

__global__ __launch_bounds__(256, 2) void sgemm_tf32_v9(
    const float* __restrict__ A1, const float* __restrict__ B1, float* __restrict__ C1,
    int nb1, int N1, int K1,
    const float* __restrict__ A2, const float* __restrict__ B2, float* __restrict__ C2,
    int nb2, int N2, int K2,
    const float* __restrict__ A3, const float* __restrict__ B3, float* __restrict__ C3,
    int N3, int K3,
    int roundC)
{
    float* Asf = dsm;
    float* Bsf = dsm + STAGES * ASZ;
    const uint32_t sbA = (uint32_t)__cvta_generic_to_shared(Asf);
    const uint32_t sbB = (uint32_t)__cvta_generic_to_shared(Bsf);

    int bx = blockIdx.x;
    const int by = blockIdx.y;
    const float* A;
    const float* B;
    float* C;
    int N, K;
    if (bx < nb1)            { A = A1; B = B1; C = C1; N = N1; K = K1; }
    else if (bx < nb1 + nb2) { A = A2; B = B2; C = C2; N = N2; K = K2; bx -= nb1; }
    else                     { A = A3; B = B3; C = C3; N = N3; K = K3; bx -= nb1 + nb2; }

    const int tid = threadIdx.x;
    const int wid = tid >> 5, lane = tid & 31;
    const int g = lane >> 2, tig = lane & 3;
    const int wm = wid & 1, wn = wid >> 1;

    const int am = tid >> 2, ak4 = (tid & 3) * 4;
    const int bk = tid >> 5, bn4 = (tid & 31) * 4;
    const float* pA0 = A + (size_t)(by * 128 + am) * K + ak4;
    const float* pA1 = pA0 + (size_t)64 * K;
    const float* pB0 = B + (size_t)bk * N + bx * 128 + bn4;
    const float* pB1 = pB0 + (size_t)8 * N;

    const uint32_t saA0 = sbA + (am * AST + ak4) * 4;
    const uint32_t saA1 = sbA + ((am + 64) * AST + ak4) * 4;
    const uint32_t saB0 = sbB + (bk * BST + bn4) * 4;
    const uint32_t saB1 = sbB + ((bk + 8) * BST + bn4) * 4;

    const uint32_t lmA = sbA + (((wm * 64 + (lane & 15)) * AST + (lane >> 4) * 4) * 4);
    const uint32_t* fB = reinterpret_cast<const uint32_t*>(Bsf) + wn * 32 + g + tig * BST;

    float acc[4][4][4];
#pragma unroll
    for (int i = 0; i < 4; i++)
#pragma unroll
        for (int j = 0; j < 4; j++)
#pragma unroll
            for (int r = 0; r < 4; r++) acc[i][j][r] = 0.f;

    const int nt = K >> 4;

#define GEMM_ISSUE(T) do {                                                    \
        if ((T) < nt) {                                                       \
            int _s = (T) % STAGES;                                            \
            int _k0 = (T) * 16;                                               \
            cpa16(saA0 + _s * ASZ * 4, pA0 + _k0);                            \
            cpa16(saA1 + _s * ASZ * 4, pA1 + _k0);                            \
            cpa16(saB0 + _s * BSZ * 4, pB0 + (size_t)_k0 * N);                \
            cpa16(saB1 + _s * BSZ * 4, pB1 + (size_t)_k0 * N);                \
        }                                                                     \
        CP_COMMIT();                                                          \
    } while (0)

#define LOAD_FRAGS(FA, FBB, SLOT, KK) do {                                    \
        const uint32_t _lA = lmA + ((SLOT) * ASZ + (KK)) * 4;                 \
        const uint32_t* _cB = fB + (SLOT) * BSZ + (KK) * BST;                 \
        _Pragma("unroll")                                                     \
        for (int i = 0; i < 4; i++)                                           \
            ldsm4(FA[i][0], FA[i][1], FA[i][2], FA[i][3],                     \
                  _lA + (i * 16 * AST) * 4);                                  \
        _Pragma("unroll")                                                     \
        for (int j = 0; j < 4; j++) {                                         \
            FBB[j][0] = _cB[j * 8];                                           \
            FBB[j][1] = _cB[4 * BST + j * 8];                                 \
        }                                                                     \
    } while (0)

#define DO_MMAS(FA, FBB) do {                                                 \
        _Pragma("unroll")                                                     \
        for (int i = 0; i < 4; i++)                                           \
            _Pragma("unroll")                                                 \
            for (int j = 0; j < 4; j++)                                       \
                mma_tf32(acc[i][j][0], acc[i][j][1], acc[i][j][2],            \
                         acc[i][j][3], FA[i][0], FA[i][1], FA[i][2],          \
                         FA[i][3], FBB[j][0], FBB[j][1]);                     \
    } while (0)

    GEMM_ISSUE(0);
    GEMM_ISSUE(1);
    GEMM_ISSUE(2);

    uint32_t fa0[4][4], fb0[4][2], fa1[4][4], fb1[4][2];

    for (int it = 0; it < nt; it += 2) {
        CP_WAITG1();
        __syncthreads();

        const int s0 = it % STAGES, s1 = (it + 1) % STAGES;

        GEMM_ISSUE(it + 3);
        LOAD_FRAGS(fa0, fb0, s0, 0);
        LOAD_FRAGS(fa1, fb1, s0, 8);
        DO_MMAS(fa0, fb0);
        LOAD_FRAGS(fa0, fb0, s1, 0);
        GEMM_ISSUE(it + 4);
        DO_MMAS(fa1, fb1);
        LOAD_FRAGS(fa1, fb1, s1, 8);
        DO_MMAS(fa0, fb0);
        DO_MMAS(fa1, fb1);
    }
#undef GEMM_ISSUE
#undef LOAD_FRAGS
#undef DO_MMAS

    float* Cb = C + (size_t)(by * 128) * N + bx * 128;
    if (roundC) {
#pragma unroll
        for (int i = 0; i < 4; i++) {
            int r0 = wm * 64 + i * 16 + g;
#pragma unroll
            for (int j = 0; j < 4; j++) {
                int cb = wn * 32 + j * 8 + tig * 2;
                uint32_t* p0 = reinterpret_cast<uint32_t*>(Cb + (size_t)r0 * N + cb);
                uint32_t* p1 = reinterpret_cast<uint32_t*>(Cb + (size_t)(r0 + 8) * N + cb);
                p0[0] = f2tf32(acc[i][j][0]); p0[1] = f2tf32(acc[i][j][1]);
                p1[0] = f2tf32(acc[i][j][2]); p1[1] = f2tf32(acc[i][j][3]);
            }
        }
    } else {
#pragma unroll
        for (int i = 0; i < 4; i++) {
            int r0 = wm * 64 + i * 16 + g;
#pragma unroll
            for (int j = 0; j < 4; j++) {
                int cb = wn * 32 + j * 8 + tig * 2;
                *reinterpret_cast<float2*>(Cb + (size_t)r0 * N + cb) =
                    make_float2(acc[i][j][0], acc[i][j][1]);
                *reinterpret_cast<float2*>(Cb + (size_t)(r0 + 8) * N + cb) =
                    make_float2(acc[i][j][2], acc[i][j][3]);
            }
        }
    }
}

// ---------------- RMSNorm (merged q/kv; writes tf32-rounded) ----------------
__global__ __launch_bounds__(256) void rmsnorm2_kernel(
    float* __restrict__ xq, const float* __restrict__ wq,
    float* __restrict__ xkv, const float* __restrict__ wkv)
{
    __shared__ float red[8];
    const int row = blockIdx.x;
    float* xr;
    const float* w;
    int D;
    if (blockIdx.y == 0) { xr = xq + (size_t)row * QR; w = wq; D = QR; }
    else                 { xr = xkv + (size_t)row * KVR; w = wkv; D = KVR; }

    float ss = 0.f;
    for (int i = threadIdx.x; i < D; i += 256) {
        float v = xr[i];
        ss += v * v;
    }
#pragma unroll
    for (int o = 16; o > 0; o >>= 1) ss += __shfl_xor_sync(0xffffffffu, ss, o);
    int wid = threadIdx.x >> 5, lid = threadIdx.x & 31;
    if (lid == 0) red[wid] = ss;
    __syncthreads();
    if (wid == 0) {
        ss = (lid < 8) ? red[lid] : 0.f;
#pragma unroll
        for (int o = 4; o > 0; o >>= 1) ss += __shfl_xor_sync(0xffffffffu, ss, o);
        if (lid == 0) red[0] = ss;
    }
    __syncthreads();
    float inv = rsqrtf(red[0] / (float)D + RMS_EPS);
    for (int i = threadIdx.x; i < D; i += 256)
        reinterpret_cast<uint32_t*>(xr)[i] = f2tf32(w[i] * xr[i] * inv);
}

// ---------------- RoPE (values pre-rounded; writes rounded) ----------------
__global__ __launch_bounds__(256) void rope_kernel(float* q, float* k)
{
    int idx = blockIdx.x * blockDim.x + threadIdx.x;
    if (idx >= SEQ * NH * 32) return;
    int j = idx & 31;
    int h = (idx >> 5) & (NH - 1);
    int s = idx >> 9;

    float invf = powf(THETA, -(float)j / 32.0f);
    float ang = (float)s * invf;
    float sn, cs;
    sincosf(ang, &sn, &cs);

    float* qp = q + ((size_t)s * NH + h) * DQ + DN;
    float x1 = qp[j], x2 = qp[j + 32];
    reinterpret_cast<uint32_t*>(qp)[j]      = f2tf32(x1 * cs - x2 * sn);
    reinterpret_cast<uint32_t*>(qp)[j + 32] = f2tf32(x2 * cs + x1 * sn);

    float* kp = k + ((size_t)s * NH + h) * DQ + DN;
    x1 = kp[j]; x2 = kp[j + 32];
    reinterpret_cast<uint32_t*>(kp)[j]      = f2tf32(x1 * cs - x2 * sn);
    reinterpret_cast<uint32_t*>(kp)[j + 32] = f2tf32(x2 * cs + x1 * sn);
}

// ---------------- tensor-core flash attention v3: PV hi-only ----------------
#define AQ 128
#define AK 32
#define QST 196
#define VST 136
#define QS_W (AQ * QST)
#define KS_W (AK * QST)
#define VS_W (AK * VST)
#define ATTN_SMEM ((QS_W + 2 * KS_W + 2 * VS_W) * 4)

__global__ __launch_bounds__(256) void attn_tf32_v3(
    const float* __restrict__ q, const float* __restrict__ kp,
    const float* __restrict__ vp, float* __restrict__ o)
{
    uint32_t* smem_u = reinterpret_cast<uint32_t*>(dsm);
    uint32_t* Qs = smem_u;
    uint32_t* Ks = smem_u + QS_W;
    uint32_t* Vs = Ks + 2 * KS_W;
    const uint32_t sbQ = (uint32_t)__cvta_generic_to_shared(Qs);
    const uint32_t sbK = (uint32_t)__cvta_generic_to_shared(Ks);
    const uint32_t sbV = (uint32_t)__cvta_generic_to_shared(Vs);

    const int qb = gridDim.x - 1 - blockIdx.x;
    const int h = blockIdx.y;
    const int tid = threadIdx.x;
    const int w = tid >> 5, lane = tid & 31;
    const int g = lane >> 2, tig = lane & 3;
    const int q0 = qb * AQ;
    const float scale = rsqrtf((float)DQ);

#define ISSUE_TILE(IT) do {                                                           \
        int _k0 = (IT) * AK; int _buf = (IT) & 1;                                     \
        _Pragma("unroll")                                                             \
        for (int _i = 0; _i < 6; _i++) {                                              \
            int _f = tid + _i * 256;                                                  \
            int _kr = _f / 48, _kc = _f % 48;                                         \
            cpa16(sbK + (_buf * KS_W + _kr * QST + _kc * 4) * 4,                      \
                  kp + ((size_t)(_k0 + _kr) * NH + h) * DQ + _kc * 4);                \
        }                                                                             \
        _Pragma("unroll")                                                             \
        for (int _i = 0; _i < 4; _i++) {                                              \
            int _f = tid + _i * 256;                                                  \
            int _vr = _f >> 5, _vc = _f & 31;                                         \
            cpa16(sbV + (_buf * VS_W + _vr * VST + _vc * 4) * 4,                      \
                  vp + ((size_t)(_k0 + _vr) * NH + h) * DV + _vc * 4);                \
        }                                                                             \
    } while (0)

    ISSUE_TILE(0);
    CP_COMMIT();

#pragma unroll
    for (int l = 0; l < 24; l++) {
        int f = tid + l * 256;
        int row = f / 48, c4 = (f % 48) * 4;
        float4 t4 = *reinterpret_cast<const float4*>(
            q + ((size_t)(q0 + row) * NH + h) * DQ + c4);
        uint4 u = make_uint4(f2tf32(t4.x * scale), f2tf32(t4.y * scale),
                             f2tf32(t4.z * scale), f2tf32(t4.w * scale));
        *reinterpret_cast<uint4*>(&Qs[row * QST + c4]) = u;
    }

    float oacc[16][4];
#pragma unroll
    for (int n = 0; n < 16; n++)
#pragma unroll
        for (int r = 0; r < 4; r++) oacc[n][r] = 0.f;
    float m0 = -1e30f, m1 = -1e30f, l0 = 0.f, l1 = 0.f;

    const uint32_t lmQ = sbQ + (((w * 16 + (lane & 15)) * QST + (lane >> 4) * 4) * 4);
    const uint32_t lmK = sbK + (((lane & 15) * QST + (lane >> 4) * 4) * 4);

    const int niter = (q0 + AQ) / AK;
    for (int it = 0; it < niter; it++) {
        const int k0g = it * AK;
        if (it + 1 < niter) ISSUE_TILE(it + 1);
        CP_COMMIT();
        CP_WAIT1();
        __syncthreads();

        const int buf = it & 1;
        const uint32_t lmK0 = lmK + buf * KS_W * 4;
        const uint32_t lmK1 = lmK0 + 16 * QST * 4;
        const uint32_t* fV = Vs + buf * VS_W + tig * VST + g;

        float s[4][4];
#pragma unroll
        for (int j = 0; j < 4; j++)
#pragma unroll
            for (int r = 0; r < 4; r++) s[j][r] = 0.f;

#pragma unroll
        for (int kt = 0; kt < 24; kt++) {
            uint32_t a0, a1, a2, a3, k00, k01, k02, k03, k10, k11, k12, k13;
            ldsm4(a0, a1, a2, a3, lmQ + kt * 32);
            ldsm4(k00, k01, k02, k03, lmK0 + kt * 32);
            ldsm4(k10, k11, k12, k13, lmK1 + kt * 32);
            mma_tf32(s[0][0], s[0][1], s[0][2], s[0][3], a0, a1, a2, a3, k00, k02);
            mma_tf32(s[1][0], s[1][1], s[1][2], s[1][3], a0, a1, a2, a3, k01, k03);
            mma_tf32(s[2][0], s[2][1], s[2][2], s[2][3], a0, a1, a2, a3, k10, k12);
            mma_tf32(s[3][0], s[3][1], s[3][2], s[3][3], a0, a1, a2, a3, k11, k13);
        }

        const int r0 = q0 + w * 16 + g, r1 = r0 + 8;
        if (k0g + AK - 1 > r0) {
#pragma unroll
            for (int j = 0; j < 4; j++) {
                int c0 = k0g + j * 8 + tig * 2, c1 = c0 + 1;
                if (c0 > r0) s[j][0] = -1e30f;
                if (c1 > r0) s[j][1] = -1e30f;
                if (c0 > r1) s[j][2] = -1e30f;
                if (c1 > r1) s[j][3] = -1e30f;
            }
        }

        float nm0 = -1e30f, nm1 = -1e30f;
#pragma unroll
        for (int j = 0; j < 4; j++) {
            nm0 = fmaxf(nm0, fmaxf(s[j][0], s[j][1]));
            nm1 = fmaxf(nm1, fmaxf(s[j][2], s[j][3]));
        }
        nm0 = fmaxf(nm0, __shfl_xor_sync(0xffffffffu, nm0, 1));
        nm0 = fmaxf(nm0, __shfl_xor_sync(0xffffffffu, nm0, 2));
        nm1 = fmaxf(nm1, __shfl_xor_sync(0xffffffffu, nm1, 1));
        nm1 = fmaxf(nm1, __shfl_xor_sync(0xffffffffu, nm1, 2));
        float mn0 = fmaxf(m0, nm0), mn1 = fmaxf(m1, nm1);
        float corr0 = fexp(m0 - mn0), corr1 = fexp(m1 - mn1);
        m0 = mn0; m1 = mn1;

        float rs0 = 0.f, rs1 = 0.f;
#pragma unroll
        for (int j = 0; j < 4; j++) {
            s[j][0] = fexp(s[j][0] - m0);
            s[j][1] = fexp(s[j][1] - m0);
            s[j][2] = fexp(s[j][2] - m1);
            s[j][3] = fexp(s[j][3] - m1);
            rs0 += s[j][0] + s[j][1];
            rs1 += s[j][2] + s[j][3];
        }
        rs0 += __shfl_xor_sync(0xffffffffu, rs0, 1);
        rs0 += __shfl_xor_sync(0xffffffffu, rs0, 2);
        rs1 += __shfl_xor_sync(0xffffffffu, rs1, 1);
        rs1 += __shfl_xor_sync(0xffffffffu, rs1, 2);
        l0 = l0 * corr0 + rs0;
        l1 = l1 * corr1 + rs1;

#pragma unroll
        for (int n = 0; n < 16; n++) {
            oacc[n][0] *= corr0; oacc[n][1] *= corr0;
            oacc[n][2] *= corr1; oacc[n][3] *= corr1;
        }

        // O += P @ V  (P rounded to tf32, single MMA per nt)
        const int src0 = (lane & 28) | (tig >> 1);
        const int src1 = src0 | 2;
        const bool bs = (tig & 1);
#pragma unroll
        for (int kt = 0; kt < 4; kt++) {
            float v00 = __shfl_sync(0xffffffffu, s[kt][0], src0);
            float v01 = __shfl_sync(0xffffffffu, s[kt][1], src0);
            float v10 = __shfl_sync(0xffffffffu, s[kt][2], src0);
            float v11 = __shfl_sync(0xffffffffu, s[kt][3], src0);
            float w00 = __shfl_sync(0xffffffffu, s[kt][0], src1);
            float w01 = __shfl_sync(0xffffffffu, s[kt][1], src1);
            float w10 = __shfl_sync(0xffffffffu, s[kt][2], src1);
            float w11 = __shfl_sync(0xffffffffu, s[kt][3], src1);
            uint32_t ah0 = f2tf32(bs ? v01 : v00);
            uint32_t ah1 = f2tf32(bs ? v11 : v10);
            uint32_t ah2 = f2tf32(bs ? w01 : w00);
            uint32_t ah3 = f2tf32(bs ? w11 : w10);
#pragma unroll
            for (int nt = 0; nt < 16; nt++) {
                uint32_t b0 = fV[kt * (8 * VST) + nt * 8];
                uint32_t b1 = fV[kt * (8 * VST) + 4 * VST + nt * 8];
                mma_tf32(oacc[nt][0], oacc[nt][1], oacc[nt][2], oacc[nt][3],
                         ah0, ah1, ah2, ah3, b0, b1);
            }
        }
        __syncthreads();
    }

    const float il0 = 1.0f / l0, il1 = 1.0f / l1;
    const int r0 = q0 + w * 16 + g, r1 = r0 + 8;
    uint32_t* o0 = reinterpret_cast<uint32_t*>(o + ((size_t)r0 * NH + h) * DV) + tig * 2;
    uint32_t* o1 = reinterpret_cast<uint32_t*>(o + ((size_t)r1 * NH + h) * DV) + tig * 2;
#pragma unroll
    for (int nt = 0; nt < 16; nt++) {
        o0[nt * 8]     = f2tf32(oacc[nt][0] * il0);
        o0[nt * 8 + 1] = f2tf32(oacc[nt][1] * il0);
        o1[nt * 8]     = f2tf32(oacc[nt][2] * il1);
        o1[nt * 8 + 1] = f2tf32(oacc[nt][3] * il1);
    }
#undef ISSUE_TILE
}

// ---------------- host launcher ----------------
extern "C" void kernel_launch(void* const* d_in, const int* in_sizes, int n_in,
                              void* d_out, int out_size)
{
    const float* x        = (const float*)d_in[0];
    const float* wq_down  = (const float*)d_in[1];
    const float* q_norm_w = (const float*)d_in[2];
    const float* wq_up    = (const float*)d_in[3];
    const float* wkv_down = (const float*)d_in[4];
    const float* kv_norm_w= (const float*)d_in[5];
    const float* wk_up    = (const float*)d_in[6];
    const float* wv_up    = (const float*)d_in[7];
    const float* wo       = (const float*)d_in[8];
    float* out = (float*)d_out;

    float *qlat, *qbuf, *kvlat, *kbuf, *vbuf, *attn;
    float *xr, *wqd, *wqu, *wkvd, *wku, *wvu, *wor;
    cudaGetSymbolAddress((void**)&qlat,  g_qlat);
    cudaGetSymbolAddress((void**)&qbuf,  g_q);
    cudaGetSymbolAddress((void**)&kvlat, g_kvlat);
    cudaGetSymbolAddress((void**)&kbuf,  g_k);
    cudaGetSymbolAddress((void**)&vbuf,  g_v);
    cudaGetSymbolAddress((void**)&attn,  g_attn);
    cudaGetSymbolAddress((void**)&xr,    g_xr);
    cudaGetSymbolAddress((void**)&wqd,   g_wqd);
    cudaGetSymbolAddress((void**)&wqu,   g_wqu);
    cudaGetSymbolAddress((void**)&wkvd,  g_wkvd);
    cudaGetSymbolAddress((void**)&wku,   g_wku);
    cudaGetSymbolAddress((void**)&wvu,   g_wvu);
    cudaGetSymbolAddress((void**)&wor,   g_wo);

    cudaFuncSetAttribute(sgemm_tf32_v9, cudaFuncAttributeMaxDynamicSharedMemorySize, GEMM_SMEM);
    cudaFuncSetAttribute(attn_tf32_v3, cudaFuncAttributeMaxDynamicSharedMemorySize, ATTN_SMEM);

    dim3 thr(256);

    // prepass: round x + all weights to tf32 (single launch)
    round_all_kernel<<<(RN6 + 255) / 256, thr>>>(
        x, wq_down, wq_up, wkv_down, wk_up, wv_up, wo);

    // down projections (merged). grid.x = 12 + 4 = 16
    sgemm_tf32_v9<<<dim3(16, SEQ / 128), thr, GEMM_SMEM>>>(
        xr, wqd, qlat, QR / 128, QR, H_DIM,
        xr, wkvd, kvlat, KVR / 128, KVR, H_DIM,
        xr, wkvd, kvlat, KVR, H_DIM,          // unused seg3
        0);

    rmsnorm2_kernel<<<dim3(SEQ, 2), thr>>>(qlat, q_norm_w, kvlat, kv_norm_w);

    // all up projections merged. grid.x = 24 + 24 + 16 = 64
    sgemm_tf32_v9<<<dim3(64, SEQ / 128), thr, GEMM_SMEM>>>(
        qlat,  wqu, qbuf, (NH * DQ) / 128, NH * DQ, QR,
        kvlat, wku, kbuf, (NH * DQ) / 128, NH * DQ, KVR,
        kvlat, wvu, vbuf, NH * DV, KVR,
        1);

    // rope (reads/writes rounded)
    rope_kernel<<<(SEQ * NH * 32) / 256, thr>>>(qbuf, kbuf);

    // causal attention, pipelined K/V, PV hi-only
    attn_tf32_v3<<<dim3(SEQ / AQ, NH), thr, ATTN_SMEM>>>(qbuf, kbuf, vbuf, attn);

    // output projection (fp32 out). grid.x = 16
    sgemm_tf32_v9<<<dim3(16, SEQ / 128), thr, GEMM_SMEM>>>(
        attn, wor, out, H_DIM / 128, H_DIM, NH * DV,
        attn, wor, out, 0, H_DIM, NH * DV,    // unused seg2
        attn, wor, out, H_DIM, NH * DV,       // unused seg3
        0);
}